// round 8
// baseline (speedup 1.0000x reference)
#include <cuda_runtime.h>
#include <math.h>
#include <stdint.h>

// Problem constants (B=2,S=2048,H=1024,I=4096,E=8)
#define NTOK 4096
#define HDIM 1024
#define IDIM 4096
#define ENUM 8

// Scratch: tf32-preconverted K-permuted operands + hmid + router weights.
__device__ float g_x32[(size_t)NTOK * HDIM];           // 16 MB
__device__ float g_w1t[(size_t)ENUM * IDIM * HDIM];    // 128 MB
__device__ float g_w2t[(size_t)ENUM * HDIM * IDIM];    // 128 MB
__device__ float g_hmid[(size_t)NTOK * IDIM];          // 64 MB (tf32 bits, permuted)
__device__ float g_w[NTOK * ENUM];

// ---------------------------------------------------------------------------
// helpers
// ---------------------------------------------------------------------------
__device__ __forceinline__ uint32_t f2tf32(float f) {
    uint32_t r;
    asm("cvt.rna.tf32.f32 %0, %1;" : "=r"(r) : "f"(f));
    return r;
}
__device__ __forceinline__ uint32_t smem_u32(const void* p) {
    uint32_t a;
    asm("{ .reg .u64 t; cvta.to.shared.u64 t, %1; cvt.u32.u64 %0, t; }"
        : "=r"(a) : "l"(p));
    return a;
}
__device__ __forceinline__ void cp_async16(uint32_t s, const void* g) {
    asm volatile("cp.async.ca.shared.global [%0], [%1], 16;" :: "r"(s), "l"(g));
}
#define CP_COMMIT() asm volatile("cp.async.commit_group;" ::: "memory")
#define CP_WAIT1()  asm volatile("cp.async.wait_group 1;" ::: "memory")

__device__ __forceinline__ void mma_tf32(float& c0, float& c1, float& c2, float& c3,
                                         uint32_t a0, uint32_t a1, uint32_t a2, uint32_t a3,
                                         uint32_t b0, uint32_t b1) {
    asm volatile(
        "mma.sync.aligned.m16n8k8.row.col.f32.tf32.tf32.f32 "
        "{%0,%1,%2,%3}, {%4,%5,%6,%7}, {%8,%9}, {%0,%1,%2,%3};"
        : "+f"(c0), "+f"(c1), "+f"(c2), "+f"(c3)
        : "r"(a0), "r"(a1), "r"(a2), "r"(a3), "r"(b0), "r"(b1));
}

// ---------------------------------------------------------------------------
// tf32 pre-conversion WITH K-chunk permutation.
// Within each 32-float K-chunk, dst position p holds src k = (p%8)*4 + p/8
// (i.e. p = (k%4)*8 + k/4). Thread writes one contiguous float4, gathers
// 4 stride-4 source floats.
// ---------------------------------------------------------------------------
__global__ void convert_perm_kernel(const float* __restrict__ src,
                                    float* __restrict__ dst, int n4) {
    int i = blockIdx.x * blockDim.x + threadIdx.x;
    int stride = gridDim.x * blockDim.x;
    for (; i < n4; i += stride) {
        const int base = i * 4;
        const int cbase = base & ~31;
        const int p0 = base & 31;            // 0,4,8,...,28
        const int t = p0 >> 3;               // p0 = 8t + 4v
        const int v = (p0 >> 2) & 1;
        const int k0 = cbase + 16 * v + t;   // k_j = 16v + 4j + t
        float4 o;
        o.x = __uint_as_float(f2tf32(src[k0]));
        o.y = __uint_as_float(f2tf32(src[k0 + 4]));
        o.z = __uint_as_float(f2tf32(src[k0 + 8]));
        o.w = __uint_as_float(f2tf32(src[k0 + 12]));
        ((float4*)dst)[i] = o;
    }
}

// ---------------------------------------------------------------------------
// Router: logits = x @ Wr^T, softmax, sort DESC (top_k with k==E semantics).
// ---------------------------------------------------------------------------
__global__ void router_kernel(const float* __restrict__ x,
                              const float* __restrict__ Wr,
                              float* __restrict__ wout) {
    int warp = (blockIdx.x * blockDim.x + threadIdx.x) >> 5;
    int lane = threadIdx.x & 31;
    if (warp >= NTOK) return;
    const float* xr = x + (size_t)warp * HDIM;

    float acc[ENUM];
#pragma unroll
    for (int e = 0; e < ENUM; e++) acc[e] = 0.f;
    for (int h = lane; h < HDIM; h += 32) {
        float xv = xr[h];
#pragma unroll
        for (int e = 0; e < ENUM; e++) acc[e] += xv * Wr[e * HDIM + h];
    }
#pragma unroll
    for (int e = 0; e < ENUM; e++) {
#pragma unroll
        for (int off = 16; off > 0; off >>= 1)
            acc[e] += __shfl_xor_sync(0xffffffffu, acc[e], off);
    }
    if (lane == 0) {
        float mx = acc[0];
#pragma unroll
        for (int e = 1; e < ENUM; e++) mx = fmaxf(mx, acc[e]);
        float s = 0.f;
#pragma unroll
        for (int e = 0; e < ENUM; e++) { acc[e] = expf(acc[e] - mx); s += acc[e]; }
        float inv = 1.f / s;
#pragma unroll
        for (int e = 0; e < ENUM; e++) acc[e] *= inv;
#define CE_DESC(a, b) { float _hi = fmaxf(a, b), _lo = fminf(a, b); (a) = _hi; (b) = _lo; }
        CE_DESC(acc[0], acc[1]); CE_DESC(acc[2], acc[3]);
        CE_DESC(acc[4], acc[5]); CE_DESC(acc[6], acc[7]);
        CE_DESC(acc[0], acc[2]); CE_DESC(acc[1], acc[3]);
        CE_DESC(acc[4], acc[6]); CE_DESC(acc[5], acc[7]);
        CE_DESC(acc[1], acc[2]); CE_DESC(acc[5], acc[6]);
        CE_DESC(acc[0], acc[4]); CE_DESC(acc[1], acc[5]);
        CE_DESC(acc[2], acc[6]); CE_DESC(acc[3], acc[7]);
        CE_DESC(acc[2], acc[4]); CE_DESC(acc[3], acc[5]);
        CE_DESC(acc[1], acc[2]); CE_DESC(acc[3], acc[4]); CE_DESC(acc[5], acc[6]);
#undef CE_DESC
#pragma unroll
        for (int e = 0; e < ENUM; e++) wout[warp * ENUM + e] = acc[e];
    }
}

// ---------------------------------------------------------------------------
// tf32 NT GEMM on K-permuted operands.
// BM=BN=128, BK=32, 256 threads (8 warps: 4Mx2N, warp tile 32x64).
// 3-stage cp.async ring, LDS.128 fragment loads, 2 CTAs/SM.
// DO_GELU: C = tf32(gelu(acc)) stored K-PERMUTED (feeds GEMM2's A);
// else:    C (+)= w[row*8+e]*acc  (plain layout).
// ---------------------------------------------------------------------------
#define BK 32
#define LDS_PITCH 36
#define TILE_FLOATS (128 * LDS_PITCH)          // 4608 floats
#define STAGE_FLOATS (2 * TILE_FLOATS)         // A + B
#define SMEM_BYTES (3 * STAGE_FLOATS * 4)      // 110592 B

template <bool DO_GELU>
__global__ __launch_bounds__(256, 2)
void tf32_gemm_kernel(const float* __restrict__ A, const float* __restrict__ B,
                      float* __restrict__ C, int K, int N,
                      const float* __restrict__ w, int e) {
    extern __shared__ float smem[];

    const int tid = threadIdx.x;
    const int wid = tid >> 5;
    const int lid = tid & 31;
    const int lq = lid >> 2;  // 0..7
    const int lr = lid & 3;   // 0..3

    const int m0 = (wid >> 1) * 32;
    const int n0 = (wid & 1) * 64;

    const int mrow0 = blockIdx.y * 128;
    const int ncol0 = blockIdx.x * 128;
    const int nchunks = K >> 5;

    const float* Abase = A + (size_t)mrow0 * K;
    const float* Bbase = B + (size_t)ncol0 * K;

    const int f4row = tid >> 3;     // 0..31
    const int f4c = (tid & 7) * 4;  // float col within 32-float chunk

    const uint32_t smem_base = smem_u32(smem);

    float acc[64];
#pragma unroll
    for (int i = 0; i < 64; i++) acc[i] = 0.f;

    auto issue = [&](int kc, int st) {
        const float* Ak = Abase + kc * BK;
        const float* Bk = Bbase + kc * BK;
        const uint32_t a_s = smem_base + (uint32_t)(st * STAGE_FLOATS) * 4u;
        const uint32_t b_s = a_s + TILE_FLOATS * 4u;
#pragma unroll
        for (int i = 0; i < 4; i++) {
            const int row = f4row + i * 32;
            const uint32_t so = (uint32_t)(row * LDS_PITCH + f4c) * 4u;
            cp_async16(a_s + so, Ak + (size_t)row * K + f4c);
            cp_async16(b_s + so, Bk + (size_t)row * K + f4c);
        }
    };

    issue(0, 0); CP_COMMIT();
    issue(1, 1); CP_COMMIT();

    for (int kc = 0; kc < nchunks; kc++) {
        CP_WAIT1();         // stage kc resident (only kc+1 may pend)
        __syncthreads();    // visible CTA-wide; stage kc-1 fully consumed
        if (kc + 2 < nchunks) {
            issue(kc + 2, (kc + 2) % 3);
            CP_COMMIT();
        }

        const float* as = smem + (kc % 3) * STAGE_FLOATS;
        const float* bs = as + TILE_FLOATS;

#pragma unroll
        for (int h = 0; h < 2; h++) {
            // A fragments for this k-half: rows (m0+im*16+lq) and +8,
            // 8 contiguous floats at col lr*8 + h*4 hold k=16h+4j+lr.
            float a4[2][2][4];
#pragma unroll
            for (int im = 0; im < 2; im++) {
                const int r = m0 + im * 16 + lq;
                *(float4*)&a4[im][0][0] =
                    *(const float4*)(as + (r)     * LDS_PITCH + lr * 8 + h * 4);
                *(float4*)&a4[im][1][0] =
                    *(const float4*)(as + (r + 8) * LDS_PITCH + lr * 8 + h * 4);
            }
#pragma unroll
            for (int nh = 0; nh < 2; nh++) {
                float b4[4][4];
#pragma unroll
                for (int jn = 0; jn < 4; jn++) {
                    const int cn = n0 + (nh * 4 + jn) * 8 + lq;
                    *(float4*)&b4[jn][0] =
                        *(const float4*)(bs + cn * LDS_PITCH + lr * 8 + h * 4);
                }
#pragma unroll
                for (int kk = 0; kk < 2; kk++)
#pragma unroll
                    for (int im = 0; im < 2; im++)
#pragma unroll
                        for (int jn = 0; jn < 4; jn++) {
                            float* c = &acc[(im * 8 + nh * 4 + jn) * 4];
                            mma_tf32(c[0], c[1], c[2], c[3],
                                     __float_as_uint(a4[im][0][2 * kk]),
                                     __float_as_uint(a4[im][1][2 * kk]),
                                     __float_as_uint(a4[im][0][2 * kk + 1]),
                                     __float_as_uint(a4[im][1][2 * kk + 1]),
                                     __float_as_uint(b4[jn][2 * kk]),
                                     __float_as_uint(b4[jn][2 * kk + 1]));
                        }
            }
        }
    }

    // ---------------- epilogue ----------------
#pragma unroll
    for (int im = 0; im < 2; im++) {
        const int row_hi = mrow0 + m0 + im * 16 + lq;
        const int row_lo = row_hi + 8;
        float s_hi = 0.f, s_lo = 0.f;
        if (!DO_GELU) {
            s_hi = w[row_hi * ENUM + e];
            s_lo = w[row_lo * ENUM + e];
        }
#pragma unroll
        for (int in_ = 0; in_ < 8; in_++) {
            const float* c = &acc[(im * 8 + in_) * 4];
            const int cb = ncol0 + n0 + in_ * 8 + 2 * lr;
            if (DO_GELU) {
                // gelu -> tf32 round -> store at K-PERMUTED position
                const int c32 = cb & 31;               // even
                const int pc0 = (cb & ~31) + ((c32 & 3) * 8 + (c32 >> 2));
                const int c32b = c32 + 1;
                const int pc1 = (cb & ~31) + ((c32b & 3) * 8 + (c32b >> 2));
                float g0 = 0.5f * c[0] * (1.0f + erff(c[0] * 0.70710678118654752f));
                float g1 = 0.5f * c[1] * (1.0f + erff(c[1] * 0.70710678118654752f));
                float g2 = 0.5f * c[2] * (1.0f + erff(c[2] * 0.70710678118654752f));
                float g3 = 0.5f * c[3] * (1.0f + erff(c[3] * 0.70710678118654752f));
                C[(size_t)row_hi * N + pc0] = __uint_as_float(f2tf32(g0));
                C[(size_t)row_hi * N + pc1] = __uint_as_float(f2tf32(g1));
                C[(size_t)row_lo * N + pc0] = __uint_as_float(f2tf32(g2));
                C[(size_t)row_lo * N + pc1] = __uint_as_float(f2tf32(g3));
            } else {
                float* p_hi = C + (size_t)row_hi * N + cb;
                float* p_lo = C + (size_t)row_lo * N + cb;
                float2 o_hi, o_lo;
                if (e == 0) {
                    o_hi = make_float2(s_hi * c[0], s_hi * c[1]);
                    o_lo = make_float2(s_lo * c[2], s_lo * c[3]);
                } else {
                    float2 d_hi = *(const float2*)p_hi;
                    float2 d_lo = *(const float2*)p_lo;
                    o_hi = make_float2(d_hi.x + s_hi * c[0], d_hi.y + s_hi * c[1]);
                    o_lo = make_float2(d_lo.x + s_lo * c[2], d_lo.y + s_lo * c[3]);
                }
                *(float2*)p_hi = o_hi;
                *(float2*)p_lo = o_lo;
            }
        }
    }
}

// ---------------------------------------------------------------------------
extern "C" void kernel_launch(void* const* d_in, const int* in_sizes, int n_in,
                              void* d_out, int out_size) {
    const float* x  = (const float*)d_in[0];  // (4096, 1024)
    const float* Wr = (const float*)d_in[1];  // (8, 1024)
    const float* W1 = (const float*)d_in[2];  // (8, 4096, 1024)
    const float* W2 = (const float*)d_in[3];  // (8, 1024, 4096)
    float* out = (float*)d_out;               // (4096, 1024)

    float *x32, *w1t, *w2t, *hmid, *wbuf;
    cudaGetSymbolAddress((void**)&x32, g_x32);
    cudaGetSymbolAddress((void**)&w1t, g_w1t);
    cudaGetSymbolAddress((void**)&w2t, g_w2t);
    cudaGetSymbolAddress((void**)&hmid, g_hmid);
    cudaGetSymbolAddress((void**)&wbuf, g_w);

    cudaFuncSetAttribute(tf32_gemm_kernel<true>,
                         cudaFuncAttributeMaxDynamicSharedMemorySize, SMEM_BYTES);
    cudaFuncSetAttribute(tf32_gemm_kernel<false>,
                         cudaFuncAttributeMaxDynamicSharedMemorySize, SMEM_BYTES);

    // Router (reads raw fp32 x)
    router_kernel<<<(NTOK * 32) / 256, 256>>>(x, Wr, wbuf);

    // tf32 pre-conversion + K-chunk permutation of x, W1, W2
    convert_perm_kernel<<<1184, 256>>>(x, x32, NTOK * HDIM / 4);
    convert_perm_kernel<<<2368, 256>>>(W1, w1t, ENUM * IDIM * HDIM / 4);
    convert_perm_kernel<<<2368, 256>>>(W2, w2t, ENUM * HDIM * IDIM / 4);

    for (int e = 0; e < ENUM; e++) {
        const float* W1e = w1t + (size_t)e * IDIM * HDIM;
        const float* W2e = w2t + (size_t)e * HDIM * IDIM;

        // GEMM1: hmid(4096x4096) = tf32(gelu(X @ W1e^T)) [K-permuted], K=1024
        {
            dim3 grid(IDIM / 128, NTOK / 128);  // (32, 32)
            tf32_gemm_kernel<true><<<grid, 256, SMEM_BYTES>>>(
                x32, W1e, hmid, HDIM, IDIM, nullptr, e);
        }
        // GEMM2: out(4096x1024) (+)= w[:,e] * (hmid @ W2e^T), K=4096
        {
            dim3 grid(HDIM / 128, NTOK / 128);  // (8, 32)
            tf32_gemm_kernel<false><<<grid, 256, SMEM_BYTES>>>(
                hmid, W2e, out, IDIM, HDIM, wbuf, e);
        }
    }
}

// round 9
// speedup vs baseline: 1.0330x; 1.0330x over previous
#include <cuda_runtime.h>
#include <math.h>
#include <stdint.h>

// Problem constants (B=2,S=2048,H=1024,I=4096,E=8)
#define NTOK 4096
#define HDIM 1024
#define IDIM 4096
#define ENUM 8

// Scratch: tf32-preconverted K-permuted operands + hmid + router weights.
__device__ float g_x32[(size_t)NTOK * HDIM];           // 16 MB
__device__ float g_w1t[(size_t)ENUM * IDIM * HDIM];    // 128 MB
__device__ float g_w2t[(size_t)ENUM * HDIM * IDIM];    // 128 MB
__device__ float g_hmid[(size_t)NTOK * IDIM];          // 64 MB (tf32 bits, K-permuted)
__device__ float g_w[NTOK * ENUM];

// ---------------------------------------------------------------------------
// helpers
// ---------------------------------------------------------------------------
__device__ __forceinline__ uint32_t f2tf32(float f) {
    uint32_t r;
    asm("cvt.rna.tf32.f32 %0, %1;" : "=r"(r) : "f"(f));
    return r;
}
__device__ __forceinline__ uint32_t smem_u32(const void* p) {
    uint32_t a;
    asm("{ .reg .u64 t; cvta.to.shared.u64 t, %1; cvt.u32.u64 %0, t; }"
        : "=r"(a) : "l"(p));
    return a;
}
__device__ __forceinline__ void cp_async16(uint32_t s, const void* g) {
    asm volatile("cp.async.ca.shared.global [%0], [%1], 16;" :: "r"(s), "l"(g));
}
#define CP_COMMIT() asm volatile("cp.async.commit_group;" ::: "memory")
#define CP_WAIT1()  asm volatile("cp.async.wait_group 1;" ::: "memory")

__device__ __forceinline__ void mma_tf32(float& c0, float& c1, float& c2, float& c3,
                                         uint32_t a0, uint32_t a1, uint32_t a2, uint32_t a3,
                                         uint32_t b0, uint32_t b1) {
    asm volatile(
        "mma.sync.aligned.m16n8k8.row.col.f32.tf32.tf32.f32 "
        "{%0,%1,%2,%3}, {%4,%5,%6,%7}, {%8,%9}, {%0,%1,%2,%3};"
        : "+f"(c0), "+f"(c1), "+f"(c2), "+f"(c3)
        : "r"(a0), "r"(a1), "r"(a2), "r"(a3), "r"(b0), "r"(b1));
}

// ---------------------------------------------------------------------------
// tf32 pre-conversion WITH K-chunk permutation.
// Within each 32-float K-chunk, dst position p holds src k with
// p = (k%4)*8 + k/4  (so a thread's 8 needed k-values are contiguous).
// ---------------------------------------------------------------------------
__global__ void convert_perm_kernel(const float* __restrict__ src,
                                    float* __restrict__ dst, int n4) {
    int i = blockIdx.x * blockDim.x + threadIdx.x;
    int stride = gridDim.x * blockDim.x;
    for (; i < n4; i += stride) {
        const int base = i * 4;
        const int cbase = base & ~31;
        const int p0 = base & 31;            // 0,4,8,...,28
        const int t = p0 >> 3;
        const int v = (p0 >> 2) & 1;
        const int k0 = cbase + 16 * v + t;   // k_j = 16v + 4j + t
        float4 o;
        o.x = __uint_as_float(f2tf32(src[k0]));
        o.y = __uint_as_float(f2tf32(src[k0 + 4]));
        o.z = __uint_as_float(f2tf32(src[k0 + 8]));
        o.w = __uint_as_float(f2tf32(src[k0 + 12]));
        ((float4*)dst)[i] = o;
    }
}

// ---------------------------------------------------------------------------
// Router: logits = x @ Wr^T, softmax, sort DESC (top_k with k==E semantics).
// ---------------------------------------------------------------------------
__global__ void router_kernel(const float* __restrict__ x,
                              const float* __restrict__ Wr,
                              float* __restrict__ wout) {
    int warp = (blockIdx.x * blockDim.x + threadIdx.x) >> 5;
    int lane = threadIdx.x & 31;
    if (warp >= NTOK) return;
    const float* xr = x + (size_t)warp * HDIM;

    float acc[ENUM];
#pragma unroll
    for (int e = 0; e < ENUM; e++) acc[e] = 0.f;
    for (int h = lane; h < HDIM; h += 32) {
        float xv = xr[h];
#pragma unroll
        for (int e = 0; e < ENUM; e++) acc[e] += xv * Wr[e * HDIM + h];
    }
#pragma unroll
    for (int e = 0; e < ENUM; e++) {
#pragma unroll
        for (int off = 16; off > 0; off >>= 1)
            acc[e] += __shfl_xor_sync(0xffffffffu, acc[e], off);
    }
    if (lane == 0) {
        float mx = acc[0];
#pragma unroll
        for (int e = 1; e < ENUM; e++) mx = fmaxf(mx, acc[e]);
        float s = 0.f;
#pragma unroll
        for (int e = 0; e < ENUM; e++) { acc[e] = expf(acc[e] - mx); s += acc[e]; }
        float inv = 1.f / s;
#pragma unroll
        for (int e = 0; e < ENUM; e++) acc[e] *= inv;
#define CE_DESC(a, b) { float _hi = fmaxf(a, b), _lo = fminf(a, b); (a) = _hi; (b) = _lo; }
        CE_DESC(acc[0], acc[1]); CE_DESC(acc[2], acc[3]);
        CE_DESC(acc[4], acc[5]); CE_DESC(acc[6], acc[7]);
        CE_DESC(acc[0], acc[2]); CE_DESC(acc[1], acc[3]);
        CE_DESC(acc[4], acc[6]); CE_DESC(acc[5], acc[7]);
        CE_DESC(acc[1], acc[2]); CE_DESC(acc[5], acc[6]);
        CE_DESC(acc[0], acc[4]); CE_DESC(acc[1], acc[5]);
        CE_DESC(acc[2], acc[6]); CE_DESC(acc[3], acc[7]);
        CE_DESC(acc[2], acc[4]); CE_DESC(acc[3], acc[5]);
        CE_DESC(acc[1], acc[2]); CE_DESC(acc[3], acc[4]); CE_DESC(acc[5], acc[6]);
#undef CE_DESC
#pragma unroll
        for (int e = 0; e < ENUM; e++) wout[warp * ENUM + e] = acc[e];
    }
}

// ---------------------------------------------------------------------------
// tf32 NT GEMM on K-permuted operands.
// BM=BN=128, BK=32, 256 threads (8 warps: 4Mx2N, warp tile 32x64).
// 3-stage cp.async ring, LDS.128 fragment loads, 2 CTAs/SM.
// DO_GELU: C = tf32(gelu(acc)), K-permuted, staged through SMEM for
//          coalesced float4 stores (feeds GEMM2's A).
// else:    C (+)= w[row*8+e]*acc  (plain layout, coalesced float2 RMW).
// ---------------------------------------------------------------------------
#define BK 32
#define LDS_PITCH 36
#define TILE_FLOATS (128 * LDS_PITCH)          // 4608 floats
#define STAGE_FLOATS (2 * TILE_FLOATS)         // A + B
#define SMEM_BYTES (3 * STAGE_FLOATS * 4)      // 110592 B
#define EPI_PITCH 132                          // 128 + 4 pad (float4-aligned)

template <bool DO_GELU>
__global__ __launch_bounds__(256, 2)
void tf32_gemm_kernel(const float* __restrict__ A, const float* __restrict__ B,
                      float* __restrict__ C, int K, int N,
                      const float* __restrict__ w, int e) {
    extern __shared__ float smem[];

    const int tid = threadIdx.x;
    const int wid = tid >> 5;
    const int lid = tid & 31;
    const int lq = lid >> 2;  // 0..7
    const int lr = lid & 3;   // 0..3

    const int m0 = (wid >> 1) * 32;
    const int n0 = (wid & 1) * 64;

    const int mrow0 = blockIdx.y * 128;
    const int ncol0 = blockIdx.x * 128;
    const int nchunks = K >> 5;

    const float* Abase = A + (size_t)mrow0 * K;
    const float* Bbase = B + (size_t)ncol0 * K;

    const int f4row = tid >> 3;     // 0..31
    const int f4c = (tid & 7) * 4;  // float col within 32-float chunk

    const uint32_t smem_base = smem_u32(smem);

    float acc[64];
#pragma unroll
    for (int i = 0; i < 64; i++) acc[i] = 0.f;

    auto issue = [&](int kc, int st) {
        const float* Ak = Abase + kc * BK;
        const float* Bk = Bbase + kc * BK;
        const uint32_t a_s = smem_base + (uint32_t)(st * STAGE_FLOATS) * 4u;
        const uint32_t b_s = a_s + TILE_FLOATS * 4u;
#pragma unroll
        for (int i = 0; i < 4; i++) {
            const int row = f4row + i * 32;
            const uint32_t so = (uint32_t)(row * LDS_PITCH + f4c) * 4u;
            cp_async16(a_s + so, Ak + (size_t)row * K + f4c);
            cp_async16(b_s + so, Bk + (size_t)row * K + f4c);
        }
    };

    issue(0, 0); CP_COMMIT();
    issue(1, 1); CP_COMMIT();

    for (int kc = 0; kc < nchunks; kc++) {
        CP_WAIT1();         // stage kc resident (only kc+1 may pend)
        __syncthreads();    // visible CTA-wide; stage kc-1 fully consumed
        if (kc + 2 < nchunks) {
            issue(kc + 2, (kc + 2) % 3);
            CP_COMMIT();
        }

        const float* as = smem + (kc % 3) * STAGE_FLOATS;
        const float* bs = as + TILE_FLOATS;

#pragma unroll
        for (int h = 0; h < 2; h++) {
            // permuted layout: 8 contiguous floats at col lr*8+h*4 hold
            // k = 16h + 4j + lr, j=0..3 (as float4: k, k+4 pairs per 2 regs)
            float a4[2][2][4];
#pragma unroll
            for (int im = 0; im < 2; im++) {
                const int r = m0 + im * 16 + lq;
                *(float4*)&a4[im][0][0] =
                    *(const float4*)(as + (r)     * LDS_PITCH + lr * 8 + h * 4);
                *(float4*)&a4[im][1][0] =
                    *(const float4*)(as + (r + 8) * LDS_PITCH + lr * 8 + h * 4);
            }
#pragma unroll
            for (int nh = 0; nh < 2; nh++) {
                float b4[4][4];
#pragma unroll
                for (int jn = 0; jn < 4; jn++) {
                    const int cn = n0 + (nh * 4 + jn) * 8 + lq;
                    *(float4*)&b4[jn][0] =
                        *(const float4*)(bs + cn * LDS_PITCH + lr * 8 + h * 4);
                }
#pragma unroll
                for (int kk = 0; kk < 2; kk++)
#pragma unroll
                    for (int im = 0; im < 2; im++)
#pragma unroll
                        for (int jn = 0; jn < 4; jn++) {
                            float* c = &acc[(im * 8 + nh * 4 + jn) * 4];
                            mma_tf32(c[0], c[1], c[2], c[3],
                                     __float_as_uint(a4[im][0][2 * kk]),
                                     __float_as_uint(a4[im][1][2 * kk]),
                                     __float_as_uint(a4[im][0][2 * kk + 1]),
                                     __float_as_uint(a4[im][1][2 * kk + 1]),
                                     __float_as_uint(b4[jn][2 * kk]),
                                     __float_as_uint(b4[jn][2 * kk + 1]));
                        }
            }
        }
    }

    // ---------------- epilogue ----------------
    if (DO_GELU) {
        // Stage gelu'd tile (K-permuted columns) in SMEM, then coalesced store.
        __syncthreads();  // mainloop smem reads complete before reuse
        float* tile = smem;  // [128][EPI_PITCH]
#pragma unroll
        for (int im = 0; im < 2; im++) {
            const int rl_hi = m0 + im * 16 + lq;
            const int rl_lo = rl_hi + 8;
#pragma unroll
            for (int in_ = 0; in_ < 8; in_++) {
                const float* c = &acc[(im * 8 + in_) * 4];
                const int cb = n0 + in_ * 8 + 2 * lr;   // tile-local col (even)
                const int c0 = cb & 31, c1 = c0 + 1;
                const int pc0 = (cb & ~31) + ((c0 & 3) * 8 + (c0 >> 2));
                const int pc1 = (cb & ~31) + ((c1 & 3) * 8 + (c1 >> 2));
                float g0 = 0.5f * c[0] * (1.0f + erff(c[0] * 0.70710678118654752f));
                float g1 = 0.5f * c[1] * (1.0f + erff(c[1] * 0.70710678118654752f));
                float g2 = 0.5f * c[2] * (1.0f + erff(c[2] * 0.70710678118654752f));
                float g3 = 0.5f * c[3] * (1.0f + erff(c[3] * 0.70710678118654752f));
                tile[rl_hi * EPI_PITCH + pc0] = __uint_as_float(f2tf32(g0));
                tile[rl_hi * EPI_PITCH + pc1] = __uint_as_float(f2tf32(g1));
                tile[rl_lo * EPI_PITCH + pc0] = __uint_as_float(f2tf32(g2));
                tile[rl_lo * EPI_PITCH + pc1] = __uint_as_float(f2tf32(g3));
            }
        }
        __syncthreads();
#pragma unroll
        for (int i = tid; i < 128 * 32; i += 256) {
            const int r = i >> 5;
            const int c = i & 31;
            float4 v = *(const float4*)&tile[r * EPI_PITCH + c * 4];
            *(float4*)&C[(size_t)(mrow0 + r) * N + ncol0 + c * 4] = v;
        }
    } else {
#pragma unroll
        for (int im = 0; im < 2; im++) {
            const int row_hi = mrow0 + m0 + im * 16 + lq;
            const int row_lo = row_hi + 8;
            const float s_hi = w[row_hi * ENUM + e];
            const float s_lo = w[row_lo * ENUM + e];
#pragma unroll
            for (int in_ = 0; in_ < 8; in_++) {
                const float* c = &acc[(im * 8 + in_) * 4];
                const int col = ncol0 + n0 + in_ * 8 + 2 * lr;
                float* p_hi = C + (size_t)row_hi * N + col;
                float* p_lo = C + (size_t)row_lo * N + col;
                float2 o_hi, o_lo;
                if (e == 0) {
                    o_hi = make_float2(s_hi * c[0], s_hi * c[1]);
                    o_lo = make_float2(s_lo * c[2], s_lo * c[3]);
                } else {
                    float2 d_hi = *(const float2*)p_hi;
                    float2 d_lo = *(const float2*)p_lo;
                    o_hi = make_float2(d_hi.x + s_hi * c[0], d_hi.y + s_hi * c[1]);
                    o_lo = make_float2(d_lo.x + s_lo * c[2], d_lo.y + s_lo * c[3]);
                }
                *(float2*)p_hi = o_hi;
                *(float2*)p_lo = o_lo;
            }
        }
    }
}

// ---------------------------------------------------------------------------
extern "C" void kernel_launch(void* const* d_in, const int* in_sizes, int n_in,
                              void* d_out, int out_size) {
    const float* x  = (const float*)d_in[0];  // (4096, 1024)
    const float* Wr = (const float*)d_in[1];  // (8, 1024)
    const float* W1 = (const float*)d_in[2];  // (8, 4096, 1024)
    const float* W2 = (const float*)d_in[3];  // (8, 1024, 4096)
    float* out = (float*)d_out;               // (4096, 1024)

    float *x32, *w1t, *w2t, *hmid, *wbuf;
    cudaGetSymbolAddress((void**)&x32, g_x32);
    cudaGetSymbolAddress((void**)&w1t, g_w1t);
    cudaGetSymbolAddress((void**)&w2t, g_w2t);
    cudaGetSymbolAddress((void**)&hmid, g_hmid);
    cudaGetSymbolAddress((void**)&wbuf, g_w);

    cudaFuncSetAttribute(tf32_gemm_kernel<true>,
                         cudaFuncAttributeMaxDynamicSharedMemorySize, SMEM_BYTES);
    cudaFuncSetAttribute(tf32_gemm_kernel<false>,
                         cudaFuncAttributeMaxDynamicSharedMemorySize, SMEM_BYTES);

    // Router (reads raw fp32 x)
    router_kernel<<<(NTOK * 32) / 256, 256>>>(x, Wr, wbuf);

    // tf32 pre-conversion + K-chunk permutation of x, W1, W2
    convert_perm_kernel<<<1184, 256>>>(x, x32, NTOK * HDIM / 4);
    convert_perm_kernel<<<2368, 256>>>(W1, w1t, ENUM * IDIM * HDIM / 4);
    convert_perm_kernel<<<2368, 256>>>(W2, w2t, ENUM * HDIM * IDIM / 4);

    for (int e = 0; e < ENUM; e++) {
        const float* W1e = w1t + (size_t)e * IDIM * HDIM;
        const float* W2e = w2t + (size_t)e * HDIM * IDIM;

        // GEMM1: hmid(4096x4096) = tf32(gelu(X @ W1e^T)) [K-permuted], K=1024
        {
            dim3 grid(IDIM / 128, NTOK / 128);  // (32, 32)
            tf32_gemm_kernel<true><<<grid, 256, SMEM_BYTES>>>(
                x32, W1e, hmid, HDIM, IDIM, nullptr, e);
        }
        // GEMM2: out(4096x1024) (+)= w[:,e] * (hmid @ W2e^T), K=4096
        {
            dim3 grid(HDIM / 128, NTOK / 128);  // (8, 32)
            tf32_gemm_kernel<false><<<grid, 256, SMEM_BYTES>>>(
                hmid, W2e, out, IDIM, HDIM, wbuf, e);
        }
    }
}

// round 11
// speedup vs baseline: 2.2061x; 2.1357x over previous
#include <cuda_runtime.h>
#include <cuda_fp16.h>
#include <math.h>
#include <stdint.h>

// Problem constants (B=2,S=2048,H=1024,I=4096,E=8)
#define NTOK 4096
#define HDIM 1024
#define IDIM 4096
#define ENUM 8

// Scratch (no cudaMalloc). float4 arrays for 16B alignment (cp.async).
__device__ float4 g_x16 [(size_t)NTOK * HDIM / 8];           // fp16 x      (8 MB)
__device__ float4 g_w1h [(size_t)ENUM * IDIM * HDIM / 8];    // fp16 W1     (64 MB)
__device__ float4 g_w2h [(size_t)ENUM * HDIM * IDIM / 8];    // fp16 W2     (64 MB)
__device__ float4 g_hmid[(size_t)ENUM * NTOK * IDIM / 8];    // fp16 scaled hmid (256 MB)
__device__ float4 g_part[(size_t)ENUM * NTOK * HDIM / 4];    // fp32 partials (128 MB)
__device__ float  g_w[NTOK * ENUM];

// ---------------------------------------------------------------------------
// helpers
// ---------------------------------------------------------------------------
__device__ __forceinline__ uint32_t smem_u32(const void* p) {
    uint32_t a;
    asm("{ .reg .u64 t; cvta.to.shared.u64 t, %1; cvt.u32.u64 %0, t; }"
        : "=r"(a) : "l"(p));
    return a;
}
__device__ __forceinline__ void cp_async16(uint32_t s, const void* g) {
    asm volatile("cp.async.ca.shared.global [%0], [%1], 16;" :: "r"(s), "l"(g));
}
#define CP_COMMIT() asm volatile("cp.async.commit_group;" ::: "memory")
#define CP_WAIT0()  asm volatile("cp.async.wait_group 0;" ::: "memory")

__device__ __forceinline__ void mma_f16(float& c0, float& c1, float& c2, float& c3,
                                        uint32_t a0, uint32_t a1, uint32_t a2, uint32_t a3,
                                        uint32_t b0, uint32_t b1) {
    asm volatile(
        "mma.sync.aligned.m16n8k16.row.col.f32.f16.f16.f32 "
        "{%0,%1,%2,%3}, {%4,%5,%6,%7}, {%8,%9}, {%0,%1,%2,%3};"
        : "+f"(c0), "+f"(c1), "+f"(c2), "+f"(c3)
        : "r"(a0), "r"(a1), "r"(a2), "r"(a3), "r"(b0), "r"(b1));
}

// ---------------------------------------------------------------------------
// fp32 -> fp16 conversion (8 floats -> one 16B half8 store per thread-iter)
// ---------------------------------------------------------------------------
__global__ void convert_f16_kernel(const float* __restrict__ src,
                                   __half* __restrict__ dst, int n8) {
    int i = blockIdx.x * blockDim.x + threadIdx.x;
    int stride = gridDim.x * blockDim.x;
    for (; i < n8; i += stride) {
        float4 v0 = ((const float4*)src)[2 * i];
        float4 v1 = ((const float4*)src)[2 * i + 1];
        __half2 h0 = __floats2half2_rn(v0.x, v0.y);
        __half2 h1 = __floats2half2_rn(v0.z, v0.w);
        __half2 h2 = __floats2half2_rn(v1.x, v1.y);
        __half2 h3 = __floats2half2_rn(v1.z, v1.w);
        uint4 o;
        o.x = *(uint32_t*)&h0; o.y = *(uint32_t*)&h1;
        o.z = *(uint32_t*)&h2; o.w = *(uint32_t*)&h3;
        ((uint4*)dst)[i] = o;
    }
}

// ---------------------------------------------------------------------------
// Router: logits = x @ Wr^T, softmax, sort DESC (top_k with k==E semantics).
// ---------------------------------------------------------------------------
__global__ void router_kernel(const float* __restrict__ x,
                              const float* __restrict__ Wr,
                              float* __restrict__ wout) {
    int warp = (blockIdx.x * blockDim.x + threadIdx.x) >> 5;
    int lane = threadIdx.x & 31;
    if (warp >= NTOK) return;
    const float* xr = x + (size_t)warp * HDIM;

    float acc[ENUM];
#pragma unroll
    for (int e = 0; e < ENUM; e++) acc[e] = 0.f;
    for (int h = lane; h < HDIM; h += 32) {
        float xv = xr[h];
#pragma unroll
        for (int e = 0; e < ENUM; e++) acc[e] += xv * Wr[e * HDIM + h];
    }
#pragma unroll
    for (int e = 0; e < ENUM; e++) {
#pragma unroll
        for (int off = 16; off > 0; off >>= 1)
            acc[e] += __shfl_xor_sync(0xffffffffu, acc[e], off);
    }
    if (lane == 0) {
        float mx = acc[0];
#pragma unroll
        for (int e = 1; e < ENUM; e++) mx = fmaxf(mx, acc[e]);
        float s = 0.f;
#pragma unroll
        for (int e = 0; e < ENUM; e++) { acc[e] = expf(acc[e] - mx); s += acc[e]; }
        float inv = 1.f / s;
#pragma unroll
        for (int e = 0; e < ENUM; e++) acc[e] *= inv;
#define CE_DESC(a, b) { float _hi = fmaxf(a, b), _lo = fminf(a, b); (a) = _hi; (b) = _lo; }
        CE_DESC(acc[0], acc[1]); CE_DESC(acc[2], acc[3]);
        CE_DESC(acc[4], acc[5]); CE_DESC(acc[6], acc[7]);
        CE_DESC(acc[0], acc[2]); CE_DESC(acc[1], acc[3]);
        CE_DESC(acc[4], acc[6]); CE_DESC(acc[5], acc[7]);
        CE_DESC(acc[1], acc[2]); CE_DESC(acc[5], acc[6]);
        CE_DESC(acc[0], acc[4]); CE_DESC(acc[1], acc[5]);
        CE_DESC(acc[2], acc[6]); CE_DESC(acc[3], acc[7]);
        CE_DESC(acc[2], acc[4]); CE_DESC(acc[3], acc[5]);
        CE_DESC(acc[1], acc[2]); CE_DESC(acc[3], acc[4]); CE_DESC(acc[5], acc[6]);
#undef CE_DESC
#pragma unroll
        for (int e = 0; e < ENUM; e++) wout[warp * ENUM + e] = acc[e];
    }
}

// ---------------------------------------------------------------------------
// fp16 NT GEMM: per blockIdx.z operand set. C[m,n] = op( sum_k A[m,k]*B[n,k] )
// BM=BN=128, BK=32, 256 threads (8 warps: 4Mx2N, warp tile 32x64), m16n8k16.
// 2-stage cp.async ring (R7-proven), 2 CTAs/SM.
// MODE 0 (GEMM1): C_half = fp16( w[row*8+z] * gelu(acc) )
// MODE 1 (GEMM2): C_float = acc  (per-expert partial, summed later)
// ---------------------------------------------------------------------------
#define BK 32
#define HPITCH 40                         // halves per row (32 + 8 pad)
#define TILE_HALFS (128 * HPITCH)         // 5120 halves = 10240 B
#define STAGE_HALFS (2 * TILE_HALFS)      // A + B
#define SMEM_BYTES (2 * STAGE_HALFS * 2)  // 40960 B

template <int MODE>
__global__ __launch_bounds__(256, 2)
void h16_gemm_kernel(const __half* __restrict__ A0, size_t strideA,
                     const __half* __restrict__ B0, size_t strideB,
                     void* __restrict__ C0, size_t strideC,
                     const float* __restrict__ w, int K, int N) {
    extern __shared__ __half smem[];

    const int z = blockIdx.z;
    const __half* A = A0 + (size_t)z * strideA;
    const __half* B = B0 + (size_t)z * strideB;

    const int tid = threadIdx.x;
    const int wid = tid >> 5;
    const int lid = tid & 31;
    const int lq = lid >> 2;  // 0..7
    const int lr = lid & 3;   // 0..3

    const int m0 = (wid >> 1) * 32;
    const int n0 = (wid & 1) * 64;

    const int mrow0 = blockIdx.y * 128;
    const int ncol0 = blockIdx.x * 128;
    const int nchunks = K >> 5;

    const __half* Abase = A + (size_t)mrow0 * K;
    const __half* Bbase = B + (size_t)ncol0 * K;

    const uint32_t smem_base = smem_u32(smem);

    float acc[64];
#pragma unroll
    for (int i = 0; i < 64; i++) acc[i] = 0.f;

    // fill map: tile = 128 rows x 4 16B-units; thread does units tid, tid+256
    auto issue = [&](int kc, int st) {
        const __half* Ak = Abase + kc * BK;
        const __half* Bk = Bbase + kc * BK;
        const uint32_t a_s = smem_base + (uint32_t)(st * STAGE_HALFS) * 2u;
        const uint32_t b_s = a_s + TILE_HALFS * 2u;
#pragma unroll
        for (int i = 0; i < 2; i++) {
            const int u = tid + i * 256;
            const int row = u >> 2;
            const int c8 = (u & 3) * 8;  // half offset
            const uint32_t so = (uint32_t)(row * HPITCH + c8) * 2u;
            cp_async16(a_s + so, Ak + (size_t)row * K + c8);
            cp_async16(b_s + so, Bk + (size_t)row * K + c8);
        }
    };

    issue(0, 0);
    CP_COMMIT();

    for (int kc = 0; kc < nchunks; kc++) {
        CP_WAIT0();
        __syncthreads();
        if (kc + 1 < nchunks) {
            issue(kc + 1, (kc + 1) & 1);
            CP_COMMIT();
        }

        const __half* as = smem + (kc & 1) * STAGE_HALFS;
        const __half* bs = as + TILE_HALFS;

#pragma unroll
        for (int kk = 0; kk < 2; kk++) {
            const int kb = kk * 16;
            uint32_t af[2][4], bf[8][2];
#pragma unroll
            for (int im = 0; im < 2; im++) {
                const int r = m0 + im * 16 + lq;
                af[im][0] = *(const uint32_t*)(as + (r)     * HPITCH + kb + 2 * lr);
                af[im][1] = *(const uint32_t*)(as + (r + 8) * HPITCH + kb + 2 * lr);
                af[im][2] = *(const uint32_t*)(as + (r)     * HPITCH + kb + 8 + 2 * lr);
                af[im][3] = *(const uint32_t*)(as + (r + 8) * HPITCH + kb + 8 + 2 * lr);
            }
#pragma unroll
            for (int o = 0; o < 8; o++) {
                const int cn = n0 + o * 8 + lq;
                bf[o][0] = *(const uint32_t*)(bs + cn * HPITCH + kb + 2 * lr);
                bf[o][1] = *(const uint32_t*)(bs + cn * HPITCH + kb + 8 + 2 * lr);
            }
#pragma unroll
            for (int im = 0; im < 2; im++)
#pragma unroll
                for (int o = 0; o < 8; o++) {
                    float* c = &acc[(im * 8 + o) * 4];
                    mma_f16(c[0], c[1], c[2], c[3],
                            af[im][0], af[im][1], af[im][2], af[im][3],
                            bf[o][0], bf[o][1]);
                }
        }
    }

    // ---------------- epilogue ----------------
#pragma unroll
    for (int im = 0; im < 2; im++) {
        const int row_hi = mrow0 + m0 + im * 16 + lq;
        const int row_lo = row_hi + 8;
        float s_hi = 1.f, s_lo = 1.f;
        if (MODE == 0) {
            s_hi = w[row_hi * ENUM + z];
            s_lo = w[row_lo * ENUM + z];
        }
#pragma unroll
        for (int o = 0; o < 8; o++) {
            const float* c = &acc[(im * 8 + o) * 4];
            const int col = ncol0 + n0 + o * 8 + 2 * lr;
            if (MODE == 0) {
                __half* Ch = (__half*)C0 + (size_t)z * strideC;
                float g0 = 0.5f * c[0] * (1.0f + erff(c[0] * 0.70710678118654752f));
                float g1 = 0.5f * c[1] * (1.0f + erff(c[1] * 0.70710678118654752f));
                float g2 = 0.5f * c[2] * (1.0f + erff(c[2] * 0.70710678118654752f));
                float g3 = 0.5f * c[3] * (1.0f + erff(c[3] * 0.70710678118654752f));
                *(__half2*)(Ch + (size_t)row_hi * N + col) =
                    __floats2half2_rn(s_hi * g0, s_hi * g1);
                *(__half2*)(Ch + (size_t)row_lo * N + col) =
                    __floats2half2_rn(s_lo * g2, s_lo * g3);
            } else {
                float* Cf = (float*)C0 + (size_t)z * strideC;
                *(float2*)(Cf + (size_t)row_hi * N + col) = make_float2(c[0], c[1]);
                *(float2*)(Cf + (size_t)row_lo * N + col) = make_float2(c[2], c[3]);
            }
        }
    }
}

// ---------------------------------------------------------------------------
// Reduce: out[i] = sum_e partial[e][i]  (float4 granularity)
// ---------------------------------------------------------------------------
__global__ void reduce_kernel(const float4* __restrict__ part,
                              float4* __restrict__ out, int n4) {
    int i = blockIdx.x * blockDim.x + threadIdx.x;
    if (i >= n4) return;
    float4 s = part[i];
#pragma unroll
    for (int e = 1; e < ENUM; e++) {
        float4 v = part[(size_t)e * n4 + i];
        s.x += v.x; s.y += v.y; s.z += v.z; s.w += v.w;
    }
    out[i] = s;
}

// ---------------------------------------------------------------------------
extern "C" void kernel_launch(void* const* d_in, const int* in_sizes, int n_in,
                              void* d_out, int out_size) {
    const float* x  = (const float*)d_in[0];  // (4096, 1024)
    const float* Wr = (const float*)d_in[1];  // (8, 1024)
    const float* W1 = (const float*)d_in[2];  // (8, 4096, 1024)
    const float* W2 = (const float*)d_in[3];  // (8, 1024, 4096)
    float* out = (float*)d_out;               // (4096, 1024)

    __half *x16, *w1h, *w2h, *hmid;
    float *part, *wbuf;
    cudaGetSymbolAddress((void**)&x16, g_x16);
    cudaGetSymbolAddress((void**)&w1h, g_w1h);
    cudaGetSymbolAddress((void**)&w2h, g_w2h);
    cudaGetSymbolAddress((void**)&hmid, g_hmid);
    cudaGetSymbolAddress((void**)&part, g_part);
    cudaGetSymbolAddress((void**)&wbuf, g_w);

    cudaFuncSetAttribute(h16_gemm_kernel<0>,
                         cudaFuncAttributeMaxDynamicSharedMemorySize, SMEM_BYTES);
    cudaFuncSetAttribute(h16_gemm_kernel<1>,
                         cudaFuncAttributeMaxDynamicSharedMemorySize, SMEM_BYTES);

    // Router (fp32 x)
    router_kernel<<<(NTOK * 32) / 256, 256>>>(x, Wr, wbuf);

    // fp16 conversions
    convert_f16_kernel<<<1184, 256>>>(x, x16, NTOK * HDIM / 8);
    convert_f16_kernel<<<2368, 256>>>(W1, w1h, ENUM * IDIM * HDIM / 8);
    convert_f16_kernel<<<2368, 256>>>(W2, w2h, ENUM * HDIM * IDIM / 8);

    // GEMM1 (all experts): hmid_e = fp16( w[:,e] * gelu(X @ W1e^T) ), K=1024
    {
        dim3 grid(IDIM / 128, NTOK / 128, ENUM);  // (32, 32, 8)
        h16_gemm_kernel<0><<<grid, 256, SMEM_BYTES>>>(
            x16, 0, w1h, (size_t)IDIM * HDIM, hmid, (size_t)NTOK * IDIM,
            wbuf, HDIM, IDIM);
    }
    // GEMM2 (all experts): part_e = hmid_e @ W2e^T, K=4096
    {
        dim3 grid(HDIM / 128, NTOK / 128, ENUM);  // (8, 32, 8)
        h16_gemm_kernel<1><<<grid, 256, SMEM_BYTES>>>(
            hmid, (size_t)NTOK * IDIM, w2h, (size_t)HDIM * IDIM,
            part, (size_t)NTOK * HDIM, nullptr, IDIM, HDIM);
    }
    // out = sum_e part_e
    reduce_kernel<<<(NTOK * HDIM / 4 + 255) / 256, 256>>>(
        (const float4*)part, (float4*)out, NTOK * HDIM / 4);
}

// round 15
// speedup vs baseline: 2.3783x; 1.0781x over previous
#include <cuda_runtime.h>
#include <cuda_fp16.h>
#include <math.h>
#include <stdint.h>

// Problem constants (B=2,S=2048,H=1024,I=4096,E=8)
#define NTOK 4096
#define HDIM 1024
#define IDIM 4096
#define ENUM 8

// Scratch (no cudaMalloc). float4 arrays for 16B alignment (cp.async).
__device__ float4 g_x16 [(size_t)NTOK * HDIM / 8];           // fp16 x      (8 MB)
__device__ float4 g_w1h [(size_t)ENUM * IDIM * HDIM / 8];    // fp16 W1     (64 MB)
__device__ float4 g_w2h [(size_t)ENUM * HDIM * IDIM / 8];    // fp16 W2     (64 MB)
__device__ float4 g_hmid[(size_t)ENUM * NTOK * IDIM / 8];    // fp16 scaled hmid (256 MB)
__device__ float  g_w[NTOK * ENUM];

// ---------------------------------------------------------------------------
// helpers
// ---------------------------------------------------------------------------
__device__ __forceinline__ uint32_t smem_u32(const void* p) {
    uint32_t a;
    asm("{ .reg .u64 t; cvta.to.shared.u64 t, %1; cvt.u32.u64 %0, t; }"
        : "=r"(a) : "l"(p));
    return a;
}
__device__ __forceinline__ void cp_async16(uint32_t s, const void* g) {
    asm volatile("cp.async.ca.shared.global [%0], [%1], 16;" :: "r"(s), "l"(g));
}
#define CP_COMMIT() asm volatile("cp.async.commit_group;" ::: "memory")
#define CP_WAIT0()  asm volatile("cp.async.wait_group 0;" ::: "memory")

__device__ __forceinline__ void mma_f16(float& c0, float& c1, float& c2, float& c3,
                                        uint32_t a0, uint32_t a1, uint32_t a2, uint32_t a3,
                                        uint32_t b0, uint32_t b1) {
    asm volatile(
        "mma.sync.aligned.m16n8k16.row.col.f32.f16.f16.f32 "
        "{%0,%1,%2,%3}, {%4,%5,%6,%7}, {%8,%9}, {%0,%1,%2,%3};"
        : "+f"(c0), "+f"(c1), "+f"(c2), "+f"(c3)
        : "r"(a0), "r"(a1), "r"(a2), "r"(a3), "r"(b0), "r"(b1));
}
__device__ __forceinline__ void ldsm_x4(uint32_t& r0, uint32_t& r1,
                                        uint32_t& r2, uint32_t& r3, uint32_t a) {
    asm volatile("ldmatrix.sync.aligned.m8n8.x4.shared.b16 {%0,%1,%2,%3}, [%4];"
                 : "=r"(r0), "=r"(r1), "=r"(r2), "=r"(r3) : "r"(a));
}

// ---------------------------------------------------------------------------
// fp32 -> fp16 conversion
// ---------------------------------------------------------------------------
__global__ void convert_f16_kernel(const float* __restrict__ src,
                                   __half* __restrict__ dst, int n8) {
    int i = blockIdx.x * blockDim.x + threadIdx.x;
    int stride = gridDim.x * blockDim.x;
    for (; i < n8; i += stride) {
        float4 v0 = ((const float4*)src)[2 * i];
        float4 v1 = ((const float4*)src)[2 * i + 1];
        __half2 h0 = __floats2half2_rn(v0.x, v0.y);
        __half2 h1 = __floats2half2_rn(v0.z, v0.w);
        __half2 h2 = __floats2half2_rn(v1.x, v1.y);
        __half2 h3 = __floats2half2_rn(v1.z, v1.w);
        uint4 o;
        o.x = *(uint32_t*)&h0; o.y = *(uint32_t*)&h1;
        o.z = *(uint32_t*)&h2; o.w = *(uint32_t*)&h3;
        ((uint4*)dst)[i] = o;
    }
}

// ---------------------------------------------------------------------------
// Router: logits = x @ Wr^T, softmax, sort DESC (top_k with k==E semantics).
// ---------------------------------------------------------------------------
__global__ void router_kernel(const float* __restrict__ x,
                              const float* __restrict__ Wr,
                              float* __restrict__ wout) {
    int warp = (blockIdx.x * blockDim.x + threadIdx.x) >> 5;
    int lane = threadIdx.x & 31;
    if (warp >= NTOK) return;
    const float* xr = x + (size_t)warp * HDIM;

    float acc[ENUM];
#pragma unroll
    for (int e = 0; e < ENUM; e++) acc[e] = 0.f;
    for (int h = lane; h < HDIM; h += 32) {
        float xv = xr[h];
#pragma unroll
        for (int e = 0; e < ENUM; e++) acc[e] += xv * Wr[e * HDIM + h];
    }
#pragma unroll
    for (int e = 0; e < ENUM; e++) {
#pragma unroll
        for (int off = 16; off > 0; off >>= 1)
            acc[e] += __shfl_xor_sync(0xffffffffu, acc[e], off);
    }
    if (lane == 0) {
        float mx = acc[0];
#pragma unroll
        for (int e = 1; e < ENUM; e++) mx = fmaxf(mx, acc[e]);
        float s = 0.f;
#pragma unroll
        for (int e = 0; e < ENUM; e++) { acc[e] = expf(acc[e] - mx); s += acc[e]; }
        float inv = 1.f / s;
#pragma unroll
        for (int e = 0; e < ENUM; e++) acc[e] *= inv;
#define CE_DESC(a, b) { float _hi = fmaxf(a, b), _lo = fminf(a, b); (a) = _hi; (b) = _lo; }
        CE_DESC(acc[0], acc[1]); CE_DESC(acc[2], acc[3]);
        CE_DESC(acc[4], acc[5]); CE_DESC(acc[6], acc[7]);
        CE_DESC(acc[0], acc[2]); CE_DESC(acc[1], acc[3]);
        CE_DESC(acc[4], acc[6]); CE_DESC(acc[5], acc[7]);
        CE_DESC(acc[1], acc[2]); CE_DESC(acc[5], acc[6]);
        CE_DESC(acc[0], acc[4]); CE_DESC(acc[1], acc[5]);
        CE_DESC(acc[2], acc[6]); CE_DESC(acc[3], acc[7]);
        CE_DESC(acc[2], acc[4]); CE_DESC(acc[3], acc[5]);
        CE_DESC(acc[1], acc[2]); CE_DESC(acc[3], acc[4]); CE_DESC(acc[5], acc[6]);
#undef CE_DESC
#pragma unroll
        for (int e = 0; e < ENUM; e++) wout[warp * ENUM + e] = acc[e];
    }
}

// ---------------------------------------------------------------------------
// Shared tile geometry: BM=BN=128, BK=32, 8 warps (4Mx2N), warp tile 32x64.
// ---------------------------------------------------------------------------
#define BK 32
#define HPITCH 40                          // halves per row (32 + 8 pad)
#define TILE_HALFS (128 * HPITCH)
#define TILE_BYTES (TILE_HALFS * 2)        // 10240
#define STAGE_BYTES (2 * TILE_BYTES)       // A + B = 20480
#define SMEM_BYTES (2 * STAGE_BYTES)       // 40960

// Fragment-load (ldmatrix) + MMA for one 32-K chunk. Emitted inline.
#define CHUNK_COMPUTE(as_base, bs_base)                                          \
    do {                                                                         \
        _Pragma("unroll")                                                        \
        for (int kk = 0; kk < 2; kk++) {                                         \
            const uint32_t kb2 = kk * 32;                                        \
            uint32_t af[2][4], bf[8][2];                                         \
            ldsm_x4(af[0][0], af[0][1], af[0][2], af[0][3],                      \
                    (as_base) + a_off0 + kb2);                                   \
            ldsm_x4(af[1][0], af[1][1], af[1][2], af[1][3],                      \
                    (as_base) + a_off1 + kb2);                                   \
            ldsm_x4(bf[0][0], bf[1][0], bf[2][0], bf[3][0],                      \
                    (bs_base) + b_off0 + kb2);                                   \
            ldsm_x4(bf[4][0], bf[5][0], bf[6][0], bf[7][0],                      \
                    (bs_base) + b_off1 + kb2);                                   \
            ldsm_x4(bf[0][1], bf[1][1], bf[2][1], bf[3][1],                      \
                    (bs_base) + b_off0 + kb2 + 16);                              \
            ldsm_x4(bf[4][1], bf[5][1], bf[6][1], bf[7][1],                      \
                    (bs_base) + b_off1 + kb2 + 16);                              \
            _Pragma("unroll")                                                    \
            for (int im = 0; im < 2; im++)                                       \
                _Pragma("unroll")                                                \
                for (int o = 0; o < 8; o++) {                                    \
                    float* c = &acc[(im * 8 + o) * 4];                           \
                    mma_f16(c[0], c[1], c[2], c[3],                              \
                            af[im][0], af[im][1], af[im][2], af[im][3],          \
                            bf[o][0], bf[o][1]);                                 \
                }                                                                \
        }                                                                        \
    } while (0)

// ---------------------------------------------------------------------------
// GEMM1 (per-expert z): hmid_z = fp16( w[:,z] * gelu( X @ W1z^T ) ), K=1024
// ---------------------------------------------------------------------------
__global__ __launch_bounds__(256, 2)
void h16_gemm1_kernel(const __half* __restrict__ A,
                      const __half* __restrict__ W1,
                      __half* __restrict__ Hm,
                      const float* __restrict__ w) {
    extern __shared__ __half smem[];
    const int z = blockIdx.z;
    const __half* B = W1 + (size_t)z * IDIM * HDIM;
    __half* C = Hm + (size_t)z * NTOK * IDIM;
    const int K = HDIM, N = IDIM;

    const int tid = threadIdx.x;
    const int wid = tid >> 5;
    const int lid = tid & 31;
    const int lq = lid >> 2;
    const int lr = lid & 3;
    const int m0 = (wid >> 1) * 32;
    const int n0 = (wid & 1) * 64;
    const int mrow0 = blockIdx.y * 128;
    const int ncol0 = blockIdx.x * 128;
    const int nchunks = K >> 5;

    const __half* Abase = A + (size_t)mrow0 * K;
    const __half* Bbase = B + (size_t)ncol0 * K;
    const uint32_t smem_base = smem_u32(smem);

    // ldmatrix per-thread byte offsets
    const uint32_t a_off0 = ((m0 + (lid & 15)) * HPITCH + (lid >> 4) * 8) * 2;
    const uint32_t a_off1 = a_off0 + 16 * HPITCH * 2;
    const uint32_t b_off0 = (uint32_t)(n0 + lid) * HPITCH * 2;
    const uint32_t b_off1 = b_off0 + 32 * HPITCH * 2;

    float acc[64];
#pragma unroll
    for (int i = 0; i < 64; i++) acc[i] = 0.f;

    auto issue = [&](int kc, int st) {
        const __half* Ak = Abase + kc * BK;
        const __half* Bk = Bbase + kc * BK;
        const uint32_t a_s = smem_base + st * STAGE_BYTES;
        const uint32_t b_s = a_s + TILE_BYTES;
#pragma unroll
        for (int i = 0; i < 2; i++) {
            const int u = tid + i * 256;
            const int row = u >> 2;
            const int c8 = (u & 3) * 8;
            const uint32_t so = (uint32_t)(row * HPITCH + c8) * 2u;
            cp_async16(a_s + so, Ak + (size_t)row * K + c8);
            cp_async16(b_s + so, Bk + (size_t)row * K + c8);
        }
    };

    issue(0, 0); CP_COMMIT();
    for (int kc = 0; kc < nchunks; kc++) {
        CP_WAIT0();
        __syncthreads();
        if (kc + 1 < nchunks) { issue(kc + 1, (kc + 1) & 1); CP_COMMIT(); }
        const uint32_t as_b = smem_base + (kc & 1) * STAGE_BYTES;
        const uint32_t bs_b = as_b + TILE_BYTES;
        CHUNK_COMPUTE(as_b, bs_b);
    }

#pragma unroll
    for (int im = 0; im < 2; im++) {
        const int row_hi = mrow0 + m0 + im * 16 + lq;
        const int row_lo = row_hi + 8;
        const float s_hi = w[row_hi * ENUM + z];
        const float s_lo = w[row_lo * ENUM + z];
#pragma unroll
        for (int o = 0; o < 8; o++) {
            const float* c = &acc[(im * 8 + o) * 4];
            const int col = ncol0 + n0 + o * 8 + 2 * lr;
            float g0 = 0.5f * c[0] * (1.0f + erff(c[0] * 0.70710678118654752f));
            float g1 = 0.5f * c[1] * (1.0f + erff(c[1] * 0.70710678118654752f));
            float g2 = 0.5f * c[2] * (1.0f + erff(c[2] * 0.70710678118654752f));
            float g3 = 0.5f * c[3] * (1.0f + erff(c[3] * 0.70710678118654752f));
            *(__half2*)(C + (size_t)row_hi * N + col) =
                __floats2half2_rn(s_hi * g0, s_hi * g1);
            *(__half2*)(C + (size_t)row_lo * N + col) =
                __floats2half2_rn(s_lo * g2, s_lo * g3);
        }
    }
}

// ---------------------------------------------------------------------------
// GEMM2 fused over experts: out = sum_e hmid_e @ W2e^T, K=8*4096 effective.
// grid (8, 32) — single wave; pure store epilogue (w folded into hmid).
// ---------------------------------------------------------------------------
__global__ __launch_bounds__(256, 2)
void h16_gemm2_kernel(const __half* __restrict__ Hm,
                      const __half* __restrict__ W2,
                      float* __restrict__ out) {
    extern __shared__ __half smem[];
    const int K = IDIM, N = HDIM;

    const int tid = threadIdx.x;
    const int wid = tid >> 5;
    const int lid = tid & 31;
    const int lq = lid >> 2;
    const int lr = lid & 3;
    const int m0 = (wid >> 1) * 32;
    const int n0 = (wid & 1) * 64;
    const int mrow0 = blockIdx.y * 128;
    const int ncol0 = blockIdx.x * 128;
    const int nch_e = K >> 5;                 // 128 chunks per expert
    const int nchunks = nch_e * ENUM;         // 1024

    const uint32_t smem_base = smem_u32(smem);
    const uint32_t a_off0 = ((m0 + (lid & 15)) * HPITCH + (lid >> 4) * 8) * 2;
    const uint32_t a_off1 = a_off0 + 16 * HPITCH * 2;
    const uint32_t b_off0 = (uint32_t)(n0 + lid) * HPITCH * 2;
    const uint32_t b_off1 = b_off0 + 32 * HPITCH * 2;

    float acc[64];
#pragma unroll
    for (int i = 0; i < 64; i++) acc[i] = 0.f;

    auto issue = [&](int kcg, int st) {
        const int e = kcg >> 7;
        const int kcl = kcg & 127;
        const __half* Ak = Hm + (size_t)e * NTOK * IDIM + (size_t)mrow0 * K + kcl * BK;
        const __half* Bk = W2 + (size_t)e * HDIM * IDIM + (size_t)ncol0 * K + kcl * BK;
        const uint32_t a_s = smem_base + st * STAGE_BYTES;
        const uint32_t b_s = a_s + TILE_BYTES;
#pragma unroll
        for (int i = 0; i < 2; i++) {
            const int u = tid + i * 256;
            const int row = u >> 2;
            const int c8 = (u & 3) * 8;
            const uint32_t so = (uint32_t)(row * HPITCH + c8) * 2u;
            cp_async16(a_s + so, Ak + (size_t)row * K + c8);
            cp_async16(b_s + so, Bk + (size_t)row * K + c8);
        }
    };

    issue(0, 0); CP_COMMIT();
    for (int kc = 0; kc < nchunks; kc++) {
        CP_WAIT0();
        __syncthreads();
        if (kc + 1 < nchunks) { issue(kc + 1, (kc + 1) & 1); CP_COMMIT(); }
        const uint32_t as_b = smem_base + (kc & 1) * STAGE_BYTES;
        const uint32_t bs_b = as_b + TILE_BYTES;
        CHUNK_COMPUTE(as_b, bs_b);
    }

#pragma unroll
    for (int im = 0; im < 2; im++) {
        const int row_hi = mrow0 + m0 + im * 16 + lq;
        const int row_lo = row_hi + 8;
#pragma unroll
        for (int o = 0; o < 8; o++) {
            const float* c = &acc[(im * 8 + o) * 4];
            const int col = ncol0 + n0 + o * 8 + 2 * lr;
            *(float2*)(out + (size_t)row_hi * N + col) = make_float2(c[0], c[1]);
            *(float2*)(out + (size_t)row_lo * N + col) = make_float2(c[2], c[3]);
        }
    }
}

// ---------------------------------------------------------------------------
extern "C" void kernel_launch(void* const* d_in, const int* in_sizes, int n_in,
                              void* d_out, int out_size) {
    const float* x  = (const float*)d_in[0];  // (4096, 1024)
    const float* Wr = (const float*)d_in[1];  // (8, 1024)
    const float* W1 = (const float*)d_in[2];  // (8, 4096, 1024)
    const float* W2 = (const float*)d_in[3];  // (8, 1024, 4096)
    float* out = (float*)d_out;               // (4096, 1024)

    __half *x16, *w1h, *w2h, *hmid;
    float *wbuf;
    cudaGetSymbolAddress((void**)&x16, g_x16);
    cudaGetSymbolAddress((void**)&w1h, g_w1h);
    cudaGetSymbolAddress((void**)&w2h, g_w2h);
    cudaGetSymbolAddress((void**)&hmid, g_hmid);
    cudaGetSymbolAddress((void**)&wbuf, g_w);

    cudaFuncSetAttribute(h16_gemm1_kernel,
                         cudaFuncAttributeMaxDynamicSharedMemorySize, SMEM_BYTES);
    cudaFuncSetAttribute(h16_gemm2_kernel,
                         cudaFuncAttributeMaxDynamicSharedMemorySize, SMEM_BYTES);

    router_kernel<<<(NTOK * 32) / 256, 256>>>(x, Wr, wbuf);

    convert_f16_kernel<<<1184, 256>>>(x, x16, NTOK * HDIM / 8);
    convert_f16_kernel<<<2368, 256>>>(W1, w1h, ENUM * IDIM * HDIM / 8);
    convert_f16_kernel<<<2368, 256>>>(W2, w2h, ENUM * HDIM * IDIM / 8);

    // GEMM1 (all experts): hmid_e = fp16( w[:,e] * gelu(X @ W1e^T) )
    {
        dim3 grid(IDIM / 128, NTOK / 128, ENUM);  // (32, 32, 8)
        h16_gemm1_kernel<<<grid, 256, SMEM_BYTES>>>(x16, w1h, hmid, wbuf);
    }
    // GEMM2 fused: out = sum_e hmid_e @ W2e^T
    {
        dim3 grid(HDIM / 128, NTOK / 128);        // (8, 32)
        h16_gemm2_kernel<<<grid, 256, SMEM_BYTES>>>(hmid, w2h, out);
    }
}